// round 7
// baseline (speedup 1.0000x reference)
#include <cuda_runtime.h>
#include <cuda_bf16.h>
#include <cstdint>

#define Q     65536
#define HH    256
#define WW    256
#define NPIX  (HH*WW)    /* 65536 */
#define MROWS (4*Q)      /* 262144 */
#define KC    288        /* conv GEMM K: 9 stages of 32 */
#define NHID  256

typedef unsigned int u32;

// ---------------- scratch (device globals; no allocation allowed) ----------
__device__ __nv_bfloat16 g_XCh[(size_t)NPIX * KC];
__device__ __nv_bfloat16 g_XCl[(size_t)NPIX * KC];
__device__ float         g_G  [(size_t)NPIX * NHID];
__device__ __nv_bfloat16 g_HAh[(size_t)MROWS * NHID];
__device__ __nv_bfloat16 g_HAl[(size_t)MROWS * NHID];
__device__ __nv_bfloat16 g_HBh[(size_t)MROWS * NHID];
__device__ __nv_bfloat16 g_HBl[(size_t)MROWS * NHID];
__device__ float g_PRED[(size_t)MROWS * 3];
__device__ float g_AREA[MROWS];
__device__ __nv_bfloat16 g_W1h[256 * KC],  g_W1l[256 * KC];
__device__ __nv_bfloat16 g_W2h[256 * 256], g_W2l[256 * 256];
__device__ __nv_bfloat16 g_W3h[256 * 256], g_W3l[256 * 256];
__device__ __nv_bfloat16 g_W4h[256 * 256], g_W4l[256 * 256];

// ---------------- helpers ---------------------------------------------------
__device__ __forceinline__ u32 pack2(float x, float y) {
    __nv_bfloat162 t = __floats2bfloat162_rn(x, y);
    return *reinterpret_cast<u32*>(&t);
}
__device__ __forceinline__ void mma_bf16(float* d, const u32* a, const u32* b) {
    asm("mma.sync.aligned.m16n8k16.row.col.f32.bf16.bf16.f32 "
        "{%0,%1,%2,%3}, {%4,%5,%6,%7}, {%8,%9}, {%0,%1,%2,%3};"
        : "+f"(d[0]), "+f"(d[1]), "+f"(d[2]), "+f"(d[3])
        : "r"(a[0]), "r"(a[1]), "r"(a[2]), "r"(a[3]), "r"(b[0]), "r"(b[1]));
}
__device__ __forceinline__ void ldsm4(u32* r, const __nv_bfloat16* p) {
    u32 a = (u32)__cvta_generic_to_shared(p);
    asm volatile("ldmatrix.sync.aligned.m8n8.x4.shared.b16 {%0,%1,%2,%3}, [%4];"
                 : "=r"(r[0]), "=r"(r[1]), "=r"(r[2]), "=r"(r[3]) : "r"(a));
}
__device__ __forceinline__ void cp16(__nv_bfloat16* s, const __nv_bfloat16* g) {
    u32 sa = (u32)__cvta_generic_to_shared(s);
    asm volatile("cp.async.cg.shared.global [%0], [%1], 16;" :: "r"(sa), "l"(g));
}
__device__ __forceinline__ void cp_commit() {
    asm volatile("cp.async.commit_group;" ::: "memory");
}
template<int N> __device__ __forceinline__ void cp_wait() {
    asm volatile("cp.async.wait_group %0;" :: "n"(N) : "memory");
}

// ---------------- W prep: transpose + bf16 hi/lo split ---------------------
__global__ void prep_w_kernel(const float* __restrict__ w, int Ksrc, int Kpad,
                              __nv_bfloat16* __restrict__ hi,
                              __nv_bfloat16* __restrict__ lo) {
    int i = blockIdx.x * 256 + threadIdx.x;
    if (i >= 256 * Kpad) return;
    int n = i / Kpad, k = i - n * Kpad;
    float v = (k < Ksrc) ? w[(size_t)k * 256 + n] : 0.f;
    __nv_bfloat16 h = __float2bfloat16(v);
    hi[i] = h;
    lo[i] = __float2bfloat16(v - __bfloat162float(h));
}

// ---------------- im2col: per-pixel 3x3 reflect patch -> bf16 hi/lo --------
__global__ void im2col_kernel(const float* __restrict__ F) {
    const int p = blockIdx.x;
    const int t = threadIdx.x;         // 0..287
    const int y0 = p >> 8, x0 = p & 255;
    int c  = t / 9;
    int k  = t - c * 9;
    int di = k / 3, dj = k - di * 3;
    int y = y0 + di - 1;
    int x = x0 + dj - 1;
    y = (y < 0) ? -y : ((y >= HH) ? 2 * HH - 2 - y : y);
    x = (x < 0) ? -x : ((x >= WW) ? 2 * WW - 2 - x : x);
    float v = F[(size_t)c * NPIX + y * WW + x];
    __nv_bfloat16 h = __float2bfloat16(v);
    g_XCh[(size_t)p * KC + t] = h;
    g_XCl[(size_t)p * KC + t] = __float2bfloat16(v - __bfloat162float(h));
}

// ---------------- combine: H1 = relu(G[p] + rel/cell terms + b1) -----------
__global__ __launch_bounds__(128)
void combine_kernel(const float* __restrict__ loc,
                    const float* __restrict__ cell,
                    const float* __restrict__ w1,
                    const float* __restrict__ b1,
                    __nv_bfloat16* __restrict__ Hh,
                    __nv_bfloat16* __restrict__ Hl) {
    const int q = blockIdx.x;
    const int s = blockIdx.y;
    const int t = threadIdx.x;

    float l0 = loc[(size_t)q * 2 + 0];
    float l1 = loc[(size_t)q * 2 + 1];
    float sy = (s & 2) ? 1.f : -1.f;
    float sx = (s & 1) ? 1.f : -1.f;
    float ly = l0 + sy * (1.f / HH) + 1e-6f;
    float lx = l1 + sx * (1.f / WW) + 1e-6f;
    ly = fminf(fmaxf(ly, -1.f + 1e-6f), 1.f - 1e-6f);
    lx = fminf(fmaxf(lx, -1.f + 1e-6f), 1.f - 1e-6f);
    int iy = (int)rintf(((ly + 1.f) * HH - 1.f) * 0.5f);
    int ix = (int)rintf(((lx + 1.f) * WW - 1.f) * 0.5f);
    iy = min(max(iy, 0), HH - 1);
    ix = min(max(ix, 0), WW - 1);
    float qy = -1.f + (2.f * iy + 1.f) / HH;
    float qx = -1.f + (2.f * ix + 1.f) / WW;
    float rel0 = (l0 - qy) * HH;
    float rel1 = (l1 - qx) * WW;
    float c0 = cell[(size_t)q * 2 + 0] * HH;
    float c1 = cell[(size_t)q * 2 + 1] * WW;

    const size_t row = (size_t)s * Q + q;
    const int p = iy * WW + ix;
    if (t == 0) g_AREA[row] = fabsf(rel0 * rel1) + 1e-9f;

    const float2* gg  = reinterpret_cast<const float2*>(g_G + (size_t)p * NHID);
    const float2* wr0 = reinterpret_cast<const float2*>(w1 + 288 * 256);
    const float2* wr1 = wr0 + 128;
    const float2* wr2 = wr1 + 128;
    const float2* wr3 = wr2 + 128;
    const float2* bb  = reinterpret_cast<const float2*>(b1);

    float2 g  = gg[t];
    float2 a0 = wr0[t], a1 = wr1[t], a2 = wr2[t], a3 = wr3[t];
    float2 bv = bb[t];
    float v0 = g.x + rel0 * a0.x + rel1 * a1.x + c0 * a2.x + c1 * a3.x + bv.x;
    float v1 = g.y + rel0 * a0.y + rel1 * a1.y + c0 * a2.y + c1 * a3.y + bv.y;
    v0 = fmaxf(v0, 0.f); v1 = fmaxf(v1, 0.f);
    float h0 = __bfloat162float(__float2bfloat16(v0));
    float h1 = __bfloat162float(__float2bfloat16(v1));
    size_t off = row * NHID + t * 2;
    *reinterpret_cast<u32*>(Hh + off) = pack2(h0, h1);
    *reinterpret_cast<u32*>(Hl + off) = pack2(v0 - h0, v1 - h1);
}

// ---------------- HMMA bf16-3x GEMM, 256x128 tile --------------------------
#define SST    40
#define APLANE (256 * SST)     /* 10240 elem */
#define BPLANE (128 * SST)     /* 5120 elem */
#define STAGE  (2 * APLANE + 2 * BPLANE)   /* 30720 elem */
#define SMEMB  (2 * STAGE * 2) /* 122880 B */

template<int K>
__device__ __forceinline__ void load_stage(
        __nv_bfloat16* st,
        const __nv_bfloat16* __restrict__ Ah, const __nv_bfloat16* __restrict__ Al,
        const __nv_bfloat16* __restrict__ Bh, const __nv_bfloat16* __restrict__ Bl,
        int m0, int n0, int kb, int tid) {
#pragma unroll
    for (int i = 0; i < 4; ++i) {
        int chunk = tid + i * 256;          // 0..1023
        int row = chunk >> 2;
        int c8  = (chunk & 3) << 3;
        size_t ga = (size_t)(m0 + row) * K + kb + c8;
        int so = row * SST + c8;
        cp16(st + so,          Ah + ga);
        cp16(st + APLANE + so, Al + ga);
    }
#pragma unroll
    for (int i = 0; i < 2; ++i) {
        int chunk = tid + i * 256;          // 0..511
        int row = chunk >> 2;
        int c8  = (chunk & 3) << 3;
        size_t gb = (size_t)(n0 + row) * K + kb + c8;
        int so = row * SST + c8;
        cp16(st + 2 * APLANE + so,          Bh + gb);
        cp16(st + 2 * APLANE + BPLANE + so, Bl + gb);
    }
}

// MODE: 0 = fp32 raw out; 1 = bias+relu -> bf16 hi/lo; 2 = bias+relu -> dot w5 -> atomicAdd pred
template<int K, int MODE>
__global__ __launch_bounds__(256, 1)
void hmma_gemm(const __nv_bfloat16* __restrict__ Ah,
               const __nv_bfloat16* __restrict__ Al,
               const __nv_bfloat16* __restrict__ Bh,
               const __nv_bfloat16* __restrict__ Bl,
               const float* __restrict__ bias,
               void* __restrict__ Cout,
               __nv_bfloat16* __restrict__ Clo,
               const float* __restrict__ w5) {
    extern __shared__ __nv_bfloat16 smem[];

    const int tid  = threadIdx.x;
    const int lane = tid & 31;
    const int wid  = tid >> 5;
    const int wm   = wid & 3;          // 4 m-groups of 64 rows
    const int wn   = wid >> 2;         // 2 n-groups of 64 cols
    const int m0   = blockIdx.x * 256;
    const int n0   = blockIdx.y * 128;
    const int lr   = lane >> 2;
    const int lq   = lane & 3;
    const int grp  = lane >> 3;
    const int rr   = lane & 7;

    const int a_row = wm * 64 + (grp & 1) * 8 + rr;
    const int a_kb  = (grp >> 1) * 8;
    const int b_row = wn * 64 + (grp >> 1) * 8 + rr;
    const int b_kb  = (grp & 1) * 8;

    float acc[4][8][4];
#pragma unroll
    for (int i = 0; i < 4; ++i)
#pragma unroll
        for (int j = 0; j < 8; ++j)
#pragma unroll
            for (int c = 0; c < 4; ++c) acc[i][j][c] = 0.f;

    constexpr int S = K / 32;
    load_stage<K>(smem, Ah, Al, Bh, Bl, m0, n0, 0, tid);
    cp_commit();

    for (int s = 0; s < S; ++s) {
        if (s + 1 < S) {
            load_stage<K>(smem + ((s + 1) & 1) * STAGE, Ah, Al, Bh, Bl,
                          m0, n0, (s + 1) * 32, tid);
            cp_commit();
            cp_wait<1>();
        } else {
            cp_wait<0>();
        }
        __syncthreads();

        const __nv_bfloat16* sAh = smem + (s & 1) * STAGE;
        const __nv_bfloat16* sAl = sAh + APLANE;
        const __nv_bfloat16* sBh = sAh + 2 * APLANE;
        const __nv_bfloat16* sBl = sBh + BPLANE;

#pragma unroll
        for (int ks = 0; ks < 32; ks += 16) {
            u32 af[4][2][4];
#pragma unroll
            for (int ti = 0; ti < 4; ++ti) {
                ldsm4(af[ti][0], sAh + (a_row + ti * 16) * SST + ks + a_kb);
                ldsm4(af[ti][1], sAl + (a_row + ti * 16) * SST + ks + a_kb);
            }
#pragma unroll
            for (int jp = 0; jp < 4; ++jp) {
                u32 bh[4], bl[4];
                ldsm4(bh, sBh + (b_row + jp * 16) * SST + ks + b_kb);
                ldsm4(bl, sBl + (b_row + jp * 16) * SST + ks + b_kb);
#pragma unroll
                for (int ti = 0; ti < 4; ++ti) {
                    mma_bf16(acc[ti][2 * jp],     af[ti][0], bh);
                    mma_bf16(acc[ti][2 * jp],     af[ti][0], bl);
                    mma_bf16(acc[ti][2 * jp],     af[ti][1], bh);
                    mma_bf16(acc[ti][2 * jp + 1], af[ti][0], bh + 2);
                    mma_bf16(acc[ti][2 * jp + 1], af[ti][0], bl + 2);
                    mma_bf16(acc[ti][2 * jp + 1], af[ti][1], bh + 2);
                }
            }
        }
        __syncthreads();
    }

    // ---- epilogue ----
    if (MODE == 0) {
        float* C = (float*)Cout;
#pragma unroll
        for (int ti = 0; ti < 4; ++ti) {
            int row0 = m0 + wm * 64 + ti * 16 + lr;
#pragma unroll
            for (int tj = 0; tj < 8; ++tj) {
                int col0 = n0 + wn * 64 + tj * 8 + lq * 2;
#pragma unroll
                for (int half = 0; half < 2; ++half) {
                    size_t off = (size_t)(row0 + half * 8) * NHID + col0;
                    *reinterpret_cast<float2*>(C + off) =
                        make_float2(acc[ti][tj][half * 2 + 0],
                                    acc[ti][tj][half * 2 + 1]);
                }
            }
        }
    } else if (MODE == 1) {
        __nv_bfloat16* Chi = (__nv_bfloat16*)Cout;
#pragma unroll
        for (int ti = 0; ti < 4; ++ti) {
            int row0 = m0 + wm * 64 + ti * 16 + lr;
#pragma unroll
            for (int tj = 0; tj < 8; ++tj) {
                int col0 = n0 + wn * 64 + tj * 8 + lq * 2;
                float b0 = bias[col0], b1 = bias[col0 + 1];
#pragma unroll
                for (int half = 0; half < 2; ++half) {
                    size_t off = (size_t)(row0 + half * 8) * NHID + col0;
                    float v0 = fmaxf(acc[ti][tj][half * 2 + 0] + b0, 0.f);
                    float v1 = fmaxf(acc[ti][tj][half * 2 + 1] + b1, 0.f);
                    float h0 = __bfloat162float(__float2bfloat16(v0));
                    float h1 = __bfloat162float(__float2bfloat16(v1));
                    *reinterpret_cast<u32*>(Chi + off) = pack2(h0, h1);
                    *reinterpret_cast<u32*>(Clo + off) = pack2(v0 - h0, v1 - h1);
                }
            }
        }
    } else {
        // MODE 2: bias + relu + dot with w5[256][3] -> g_PRED (atomicAdd across 2 n-CTAs)
        float part[4][2][3];
#pragma unroll
        for (int ti = 0; ti < 4; ++ti)
#pragma unroll
            for (int h = 0; h < 2; ++h)
#pragma unroll
                for (int c = 0; c < 3; ++c) part[ti][h][c] = 0.f;

#pragma unroll
        for (int tj = 0; tj < 8; ++tj) {
            int col0 = n0 + wn * 64 + tj * 8 + lq * 2;
            float b0 = bias[col0], b1 = bias[col0 + 1];
            float w50[3], w51[3];
#pragma unroll
            for (int c = 0; c < 3; ++c) {
                w50[c] = w5[col0 * 3 + c];
                w51[c] = w5[(col0 + 1) * 3 + c];
            }
#pragma unroll
            for (int ti = 0; ti < 4; ++ti)
#pragma unroll
                for (int half = 0; half < 2; ++half) {
                    float v0 = fmaxf(acc[ti][tj][half * 2 + 0] + b0, 0.f);
                    float v1 = fmaxf(acc[ti][tj][half * 2 + 1] + b1, 0.f);
#pragma unroll
                    for (int c = 0; c < 3; ++c)
                        part[ti][half][c] += v0 * w50[c] + v1 * w51[c];
                }
        }
        // reduce over lq (lanes lr*4+lq)
#pragma unroll
        for (int ti = 0; ti < 4; ++ti)
#pragma unroll
            for (int h = 0; h < 2; ++h)
#pragma unroll
                for (int c = 0; c < 3; ++c) {
                    float v = part[ti][h][c];
                    v += __shfl_xor_sync(0xffffffffu, v, 1);
                    v += __shfl_xor_sync(0xffffffffu, v, 2);
                    part[ti][h][c] = v;
                }
        float* sp = reinterpret_cast<float*>(smem);   // [2][256][3]
        if (lq == 0) {
#pragma unroll
            for (int ti = 0; ti < 4; ++ti)
#pragma unroll
                for (int h = 0; h < 2; ++h) {
                    int row = wm * 64 + ti * 16 + h * 8 + lr;
#pragma unroll
                    for (int c = 0; c < 3; ++c)
                        sp[(wn * 256 + row) * 3 + c] = part[ti][h][c];
                }
        }
        __syncthreads();
        for (int i = tid; i < 768; i += 256) {
            float v = sp[i] + sp[768 + i];
            atomicAdd(&g_PRED[(size_t)(m0 + i / 3) * 3 + (i % 3)], v);
        }
    }
}

// ---------------- output combine --------------------------------------------
__global__ __launch_bounds__(256)
void out_combine(const float* __restrict__ b5, float* __restrict__ out) {
    int q = blockIdx.x * 256 + threadIdx.x;
    float ar[4], tot = 0.f;
#pragma unroll
    for (int s = 0; s < 4; ++s) { ar[s] = g_AREA[(size_t)s * Q + q]; tot += ar[s]; }
    float r0 = 0.f, r1 = 0.f, r2 = 0.f;
#pragma unroll
    for (int s = 0; s < 4; ++s) {
        float wgt = ar[3 - s] / tot;
        size_t base = ((size_t)s * Q + q) * 3;
        r0 += (g_PRED[base + 0] + b5[0]) * wgt;
        r1 += (g_PRED[base + 1] + b5[1]) * wgt;
        r2 += (g_PRED[base + 2] + b5[2]) * wgt;
    }
    out[(size_t)q * 3 + 0] = r0;
    out[(size_t)q * 3 + 1] = r1;
    out[(size_t)q * 3 + 2] = r2;
}

// ---------------- launch ----------------------------------------------------
extern "C" void kernel_launch(void* const* d_in, const int* in_sizes, int n_in,
                              void* d_out, int out_size) {
    const float* F    = (const float*)d_in[0];
    const float* loc  = (const float*)d_in[1];
    const float* cell = (const float*)d_in[2];
    const float* w1 = (const float*)d_in[3];
    const float* b1 = (const float*)d_in[4];
    const float* w2 = (const float*)d_in[5];
    const float* b2 = (const float*)d_in[6];
    const float* w3 = (const float*)d_in[7];
    const float* b3 = (const float*)d_in[8];
    const float* w4 = (const float*)d_in[9];
    const float* b4 = (const float*)d_in[10];
    const float* w5 = (const float*)d_in[11];
    const float* b5 = (const float*)d_in[12];
    float* out = (float*)d_out;

    __nv_bfloat16 *XCh, *XCl, *HAh, *HAl, *HBh, *HBl;
    __nv_bfloat16 *W1h, *W1l, *W2h, *W2l, *W3h, *W3l, *W4h, *W4l;
    float *G, *PRED;
    cudaGetSymbolAddress((void**)&XCh, g_XCh); cudaGetSymbolAddress((void**)&XCl, g_XCl);
    cudaGetSymbolAddress((void**)&G,   g_G);
    cudaGetSymbolAddress((void**)&PRED, g_PRED);
    cudaGetSymbolAddress((void**)&HAh, g_HAh); cudaGetSymbolAddress((void**)&HAl, g_HAl);
    cudaGetSymbolAddress((void**)&HBh, g_HBh); cudaGetSymbolAddress((void**)&HBl, g_HBl);
    cudaGetSymbolAddress((void**)&W1h, g_W1h); cudaGetSymbolAddress((void**)&W1l, g_W1l);
    cudaGetSymbolAddress((void**)&W2h, g_W2h); cudaGetSymbolAddress((void**)&W2l, g_W2l);
    cudaGetSymbolAddress((void**)&W3h, g_W3h); cudaGetSymbolAddress((void**)&W3l, g_W3l);
    cudaGetSymbolAddress((void**)&W4h, g_W4h); cudaGetSymbolAddress((void**)&W4l, g_W4l);

    cudaFuncSetAttribute(hmma_gemm<KC, 0>,
        cudaFuncAttributeMaxDynamicSharedMemorySize, SMEMB);
    cudaFuncSetAttribute(hmma_gemm<256, 1>,
        cudaFuncAttributeMaxDynamicSharedMemorySize, SMEMB);
    cudaFuncSetAttribute(hmma_gemm<256, 2>,
        cudaFuncAttributeMaxDynamicSharedMemorySize, SMEMB);

    prep_w_kernel<<<(256 * KC  + 255) / 256, 256>>>(w1, KC,  KC,  W1h, W1l);
    prep_w_kernel<<<(256 * 256 + 255) / 256, 256>>>(w2, 256, 256, W2h, W2l);
    prep_w_kernel<<<(256 * 256 + 255) / 256, 256>>>(w3, 256, 256, W3h, W3l);
    prep_w_kernel<<<(256 * 256 + 255) / 256, 256>>>(w4, 256, 256, W4h, W4l);

    im2col_kernel<<<NPIX, KC>>>(F);

    // conv GEMM: G[65536,256] = XC @ W1[0:288]^T
    hmma_gemm<KC, 0><<<dim3(NPIX / 256, 2), 256, SMEMB>>>(
        XCh, XCl, W1h, W1l, nullptr, G, nullptr, nullptr);

    combine_kernel<<<dim3(Q, 4), 128>>>(loc, cell, w1, b1, HAh, HAl);

    cudaMemsetAsync(PRED, 0, (size_t)MROWS * 3 * sizeof(float));

    dim3 ggrid(MROWS / 256, 2);
    hmma_gemm<256, 1><<<ggrid, 256, SMEMB>>>(HAh, HAl, W2h, W2l, b2, HBh, HBl, nullptr);
    hmma_gemm<256, 1><<<ggrid, 256, SMEMB>>>(HBh, HBl, W3h, W3l, b3, HAh, HAl, nullptr);
    hmma_gemm<256, 2><<<ggrid, 256, SMEMB>>>(HAh, HAl, W4h, W4l, b4, nullptr, nullptr, w5);

    out_combine<<<Q / 256, 256>>>(b5, out);
}

// round 8
// speedup vs baseline: 1.6490x; 1.6490x over previous
#include <cuda_runtime.h>
#include <cuda_bf16.h>
#include <cstdint>

#define Q     65536
#define HH    256
#define WW    256
#define NPIX  (HH*WW)    /* 65536 */
#define MROWS (4*Q)      /* 262144 */
#define KC    288        /* conv GEMM K: 9 stages of 32 */
#define NHID  256

typedef unsigned int u32;

// ---------------- scratch (device globals; no allocation allowed) ----------
__device__ __nv_bfloat16 g_XCh[(size_t)NPIX * KC];
__device__ __nv_bfloat16 g_XCl[(size_t)NPIX * KC];
__device__ float         g_G  [(size_t)NPIX * NHID];
__device__ __nv_bfloat16 g_HAh[(size_t)MROWS * NHID];
__device__ __nv_bfloat16 g_HAl[(size_t)MROWS * NHID];
__device__ __nv_bfloat16 g_HBh[(size_t)MROWS * NHID];
__device__ __nv_bfloat16 g_HBl[(size_t)MROWS * NHID];
__device__ float g_PRED[(size_t)MROWS * 3];
__device__ float g_AREA[MROWS];
__device__ __nv_bfloat16 g_W1h[256 * KC],  g_W1l[256 * KC];
__device__ __nv_bfloat16 g_W2h[256 * 256], g_W2l[256 * 256];
__device__ __nv_bfloat16 g_W3h[256 * 256], g_W3l[256 * 256];
__device__ __nv_bfloat16 g_W4h[256 * 256], g_W4l[256 * 256];

// ---------------- helpers ---------------------------------------------------
__device__ __forceinline__ u32 pack2(float x, float y) {
    __nv_bfloat162 t = __floats2bfloat162_rn(x, y);
    return *reinterpret_cast<u32*>(&t);
}
__device__ __forceinline__ void mma_bf16(float* d, const u32* a, const u32* b) {
    asm("mma.sync.aligned.m16n8k16.row.col.f32.bf16.bf16.f32 "
        "{%0,%1,%2,%3}, {%4,%5,%6,%7}, {%8,%9}, {%0,%1,%2,%3};"
        : "+f"(d[0]), "+f"(d[1]), "+f"(d[2]), "+f"(d[3])
        : "r"(a[0]), "r"(a[1]), "r"(a[2]), "r"(a[3]), "r"(b[0]), "r"(b[1]));
}
__device__ __forceinline__ void ldsm4(u32* r, const __nv_bfloat16* p) {
    u32 a = (u32)__cvta_generic_to_shared(p);
    asm volatile("ldmatrix.sync.aligned.m8n8.x4.shared.b16 {%0,%1,%2,%3}, [%4];"
                 : "=r"(r[0]), "=r"(r[1]), "=r"(r[2]), "=r"(r[3]) : "r"(a));
}
__device__ __forceinline__ void cp16(__nv_bfloat16* s, const __nv_bfloat16* g) {
    u32 sa = (u32)__cvta_generic_to_shared(s);
    asm volatile("cp.async.cg.shared.global [%0], [%1], 16;" :: "r"(sa), "l"(g));
}
__device__ __forceinline__ void cp_commit() {
    asm volatile("cp.async.commit_group;" ::: "memory");
}
template<int N> __device__ __forceinline__ void cp_wait() {
    asm volatile("cp.async.wait_group %0;" :: "n"(N) : "memory");
}

// ---------------- W prep: transpose + bf16 hi/lo split ---------------------
__global__ void prep_w_kernel(const float* __restrict__ w, int Ksrc, int Kpad,
                              __nv_bfloat16* __restrict__ hi,
                              __nv_bfloat16* __restrict__ lo) {
    int i = blockIdx.x * 256 + threadIdx.x;
    if (i >= 256 * Kpad) return;
    int n = i / Kpad, k = i - n * Kpad;
    float v = (k < Ksrc) ? w[(size_t)k * 256 + n] : 0.f;
    __nv_bfloat16 h = __float2bfloat16(v);
    hi[i] = h;
    lo[i] = __float2bfloat16(v - __bfloat162float(h));
}

// ---------------- im2col: per-pixel 3x3 reflect patch -> bf16 hi/lo --------
__global__ void im2col_kernel(const float* __restrict__ F) {
    const int p = blockIdx.x;
    const int t = threadIdx.x;         // 0..287
    const int y0 = p >> 8, x0 = p & 255;
    int c  = t / 9;
    int k  = t - c * 9;
    int di = k / 3, dj = k - di * 3;
    int y = y0 + di - 1;
    int x = x0 + dj - 1;
    y = (y < 0) ? -y : ((y >= HH) ? 2 * HH - 2 - y : y);
    x = (x < 0) ? -x : ((x >= WW) ? 2 * WW - 2 - x : x);
    float v = F[(size_t)c * NPIX + y * WW + x];
    __nv_bfloat16 h = __float2bfloat16(v);
    g_XCh[(size_t)p * KC + t] = h;
    g_XCl[(size_t)p * KC + t] = __float2bfloat16(v - __bfloat162float(h));
}

// ---------------- combine: H1 = relu(G[p] + rel/cell terms + b1) -----------
__global__ __launch_bounds__(128)
void combine_kernel(const float* __restrict__ loc,
                    const float* __restrict__ cell,
                    const float* __restrict__ w1,
                    const float* __restrict__ b1,
                    __nv_bfloat16* __restrict__ Hh,
                    __nv_bfloat16* __restrict__ Hl) {
    const int q = blockIdx.x;
    const int s = blockIdx.y;
    const int t = threadIdx.x;

    float l0 = loc[(size_t)q * 2 + 0];
    float l1 = loc[(size_t)q * 2 + 1];
    float sy = (s & 2) ? 1.f : -1.f;
    float sx = (s & 1) ? 1.f : -1.f;
    float ly = l0 + sy * (1.f / HH) + 1e-6f;
    float lx = l1 + sx * (1.f / WW) + 1e-6f;
    ly = fminf(fmaxf(ly, -1.f + 1e-6f), 1.f - 1e-6f);
    lx = fminf(fmaxf(lx, -1.f + 1e-6f), 1.f - 1e-6f);
    int iy = (int)rintf(((ly + 1.f) * HH - 1.f) * 0.5f);
    int ix = (int)rintf(((lx + 1.f) * WW - 1.f) * 0.5f);
    iy = min(max(iy, 0), HH - 1);
    ix = min(max(ix, 0), WW - 1);
    float qy = -1.f + (2.f * iy + 1.f) / HH;
    float qx = -1.f + (2.f * ix + 1.f) / WW;
    float rel0 = (l0 - qy) * HH;
    float rel1 = (l1 - qx) * WW;
    float c0 = cell[(size_t)q * 2 + 0] * HH;
    float c1 = cell[(size_t)q * 2 + 1] * WW;

    const size_t row = (size_t)s * Q + q;
    const int p = iy * WW + ix;
    if (t == 0) g_AREA[row] = fabsf(rel0 * rel1) + 1e-9f;

    const float2* gg  = reinterpret_cast<const float2*>(g_G + (size_t)p * NHID);
    const float2* wr0 = reinterpret_cast<const float2*>(w1 + 288 * 256);
    const float2* wr1 = wr0 + 128;
    const float2* wr2 = wr1 + 128;
    const float2* wr3 = wr2 + 128;
    const float2* bb  = reinterpret_cast<const float2*>(b1);

    float2 g  = gg[t];
    float2 a0 = wr0[t], a1 = wr1[t], a2 = wr2[t], a3 = wr3[t];
    float2 bv = bb[t];
    float v0 = g.x + rel0 * a0.x + rel1 * a1.x + c0 * a2.x + c1 * a3.x + bv.x;
    float v1 = g.y + rel0 * a0.y + rel1 * a1.y + c0 * a2.y + c1 * a3.y + bv.y;
    v0 = fmaxf(v0, 0.f); v1 = fmaxf(v1, 0.f);
    float h0 = __bfloat162float(__float2bfloat16(v0));
    float h1 = __bfloat162float(__float2bfloat16(v1));
    size_t off = row * NHID + t * 2;
    *reinterpret_cast<u32*>(Hh + off) = pack2(h0, h1);
    *reinterpret_cast<u32*>(Hl + off) = pack2(v0 - h0, v1 - h1);
}

// ---------------- HMMA bf16-3x GEMM, 128x128 tile (R5 shape) ---------------
#define SST    40
#define PLANE  (128 * SST)
#define STAGE  (4 * PLANE)     /* Ah,Al,Bh,Bl */
#define SMEMB  (2 * STAGE * 2) /* 81920 B */

template<int K>
__device__ __forceinline__ void load_stage(
        __nv_bfloat16* st,
        const __nv_bfloat16* __restrict__ Ah, const __nv_bfloat16* __restrict__ Al,
        const __nv_bfloat16* __restrict__ Bh, const __nv_bfloat16* __restrict__ Bl,
        int m0, int n0, int kb, int tid) {
#pragma unroll
    for (int i = 0; i < 2; ++i) {
        int chunk = tid + i * 256;
        int row = chunk >> 2;
        int c8  = (chunk & 3) << 3;
        size_t ga = (size_t)(m0 + row) * K + kb + c8;
        size_t gb = (size_t)(n0 + row) * K + kb + c8;
        int so = row * SST + c8;
        cp16(st + so,             Ah + ga);
        cp16(st + PLANE + so,     Al + ga);
        cp16(st + 2 * PLANE + so, Bh + gb);
        cp16(st + 3 * PLANE + so, Bl + gb);
    }
}

// MODE: 0 = fp32 raw out; 1 = bias+relu -> bf16 hi/lo; 2 = bias+relu -> dot w5 -> atomicAdd
template<int K, int MODE>
__global__ __launch_bounds__(256, 2)
void hmma_gemm(const __nv_bfloat16* __restrict__ Ah,
               const __nv_bfloat16* __restrict__ Al,
               const __nv_bfloat16* __restrict__ Bh,
               const __nv_bfloat16* __restrict__ Bl,
               const float* __restrict__ bias,
               void* __restrict__ Cout,
               __nv_bfloat16* __restrict__ Clo,
               const float* __restrict__ w5) {
    extern __shared__ __nv_bfloat16 smem[];

    const int tid  = threadIdx.x;
    const int lane = tid & 31;
    const int wid  = tid >> 5;
    const int wm   = wid & 3;
    const int wn   = wid >> 2;
    const int m0   = blockIdx.x * 128;
    const int n0   = blockIdx.y * 128;
    const int lr   = lane >> 2;
    const int lq   = lane & 3;
    const int grp  = lane >> 3;
    const int rr   = lane & 7;

    const int a_row = wm * 32 + (grp & 1) * 8 + rr;
    const int a_kb  = (grp >> 1) * 8;
    const int b_row = wn * 64 + (grp >> 1) * 8 + rr;
    const int b_kb  = (grp & 1) * 8;

    float acc[2][8][4];
#pragma unroll
    for (int i = 0; i < 2; ++i)
#pragma unroll
        for (int j = 0; j < 8; ++j)
#pragma unroll
            for (int c = 0; c < 4; ++c) acc[i][j][c] = 0.f;

    constexpr int S = K / 32;
    load_stage<K>(smem, Ah, Al, Bh, Bl, m0, n0, 0, tid);
    cp_commit();

    for (int s = 0; s < S; ++s) {
        if (s + 1 < S) {
            load_stage<K>(smem + ((s + 1) & 1) * STAGE, Ah, Al, Bh, Bl,
                          m0, n0, (s + 1) * 32, tid);
            cp_commit();
            cp_wait<1>();
        } else {
            cp_wait<0>();
        }
        __syncthreads();

        const __nv_bfloat16* sAh = smem + (s & 1) * STAGE;
        const __nv_bfloat16* sAl = sAh + PLANE;
        const __nv_bfloat16* sBh = sAh + 2 * PLANE;
        const __nv_bfloat16* sBl = sAh + 3 * PLANE;

#pragma unroll
        for (int ks = 0; ks < 32; ks += 16) {
            u32 af[2][2][4];
#pragma unroll
            for (int ti = 0; ti < 2; ++ti) {
                ldsm4(af[ti][0], sAh + (a_row + ti * 16) * SST + ks + a_kb);
                ldsm4(af[ti][1], sAl + (a_row + ti * 16) * SST + ks + a_kb);
            }
#pragma unroll
            for (int jp = 0; jp < 4; ++jp) {
                u32 bh[4], bl[4];
                ldsm4(bh, sBh + (b_row + jp * 16) * SST + ks + b_kb);
                ldsm4(bl, sBl + (b_row + jp * 16) * SST + ks + b_kb);
#pragma unroll
                for (int ti = 0; ti < 2; ++ti) {
                    mma_bf16(acc[ti][2 * jp],     af[ti][0], bh);
                    mma_bf16(acc[ti][2 * jp],     af[ti][0], bl);
                    mma_bf16(acc[ti][2 * jp],     af[ti][1], bh);
                    mma_bf16(acc[ti][2 * jp + 1], af[ti][0], bh + 2);
                    mma_bf16(acc[ti][2 * jp + 1], af[ti][0], bl + 2);
                    mma_bf16(acc[ti][2 * jp + 1], af[ti][1], bh + 2);
                }
            }
        }
        __syncthreads();
    }

    // ---- epilogue ----
    if (MODE == 0) {
        float* C = (float*)Cout;
#pragma unroll
        for (int ti = 0; ti < 2; ++ti) {
            int row0 = m0 + wm * 32 + ti * 16 + lr;
#pragma unroll
            for (int tj = 0; tj < 8; ++tj) {
                int col0 = n0 + wn * 64 + tj * 8 + lq * 2;
#pragma unroll
                for (int half = 0; half < 2; ++half) {
                    size_t off = (size_t)(row0 + half * 8) * NHID + col0;
                    *reinterpret_cast<float2*>(C + off) =
                        make_float2(acc[ti][tj][half * 2 + 0],
                                    acc[ti][tj][half * 2 + 1]);
                }
            }
        }
    } else if (MODE == 1) {
        __nv_bfloat16* Chi = (__nv_bfloat16*)Cout;
#pragma unroll
        for (int ti = 0; ti < 2; ++ti) {
            int row0 = m0 + wm * 32 + ti * 16 + lr;
#pragma unroll
            for (int tj = 0; tj < 8; ++tj) {
                int col0 = n0 + wn * 64 + tj * 8 + lq * 2;
                float b0 = bias[col0], b1 = bias[col0 + 1];
#pragma unroll
                for (int half = 0; half < 2; ++half) {
                    size_t off = (size_t)(row0 + half * 8) * NHID + col0;
                    float v0 = fmaxf(acc[ti][tj][half * 2 + 0] + b0, 0.f);
                    float v1 = fmaxf(acc[ti][tj][half * 2 + 1] + b1, 0.f);
                    float h0 = __bfloat162float(__float2bfloat16(v0));
                    float h1 = __bfloat162float(__float2bfloat16(v1));
                    *reinterpret_cast<u32*>(Chi + off) = pack2(h0, h1);
                    *reinterpret_cast<u32*>(Clo + off) = pack2(v0 - h0, v1 - h1);
                }
            }
        }
    } else {
        // MODE 2: bias + relu + dot with w5[256][3] -> g_PRED (atomicAdd over 2 n-CTAs)
        float part[2][2][3];
#pragma unroll
        for (int ti = 0; ti < 2; ++ti)
#pragma unroll
            for (int h = 0; h < 2; ++h)
#pragma unroll
                for (int c = 0; c < 3; ++c) part[ti][h][c] = 0.f;

#pragma unroll
        for (int tj = 0; tj < 8; ++tj) {
            int col0 = n0 + wn * 64 + tj * 8 + lq * 2;
            float b0 = bias[col0], b1 = bias[col0 + 1];
            float w50[3], w51[3];
#pragma unroll
            for (int c = 0; c < 3; ++c) {
                w50[c] = w5[col0 * 3 + c];
                w51[c] = w5[(col0 + 1) * 3 + c];
            }
#pragma unroll
            for (int ti = 0; ti < 2; ++ti)
#pragma unroll
                for (int half = 0; half < 2; ++half) {
                    float v0 = fmaxf(acc[ti][tj][half * 2 + 0] + b0, 0.f);
                    float v1 = fmaxf(acc[ti][tj][half * 2 + 1] + b1, 0.f);
#pragma unroll
                    for (int c = 0; c < 3; ++c)
                        part[ti][half][c] += v0 * w50[c] + v1 * w51[c];
                }
        }
#pragma unroll
        for (int ti = 0; ti < 2; ++ti)
#pragma unroll
            for (int h = 0; h < 2; ++h)
#pragma unroll
                for (int c = 0; c < 3; ++c) {
                    float v = part[ti][h][c];
                    v += __shfl_xor_sync(0xffffffffu, v, 1);
                    v += __shfl_xor_sync(0xffffffffu, v, 2);
                    part[ti][h][c] = v;
                }
        float* sp = reinterpret_cast<float*>(smem);   // [2][128][3] = 768 floats
        if (lq == 0) {
#pragma unroll
            for (int ti = 0; ti < 2; ++ti)
#pragma unroll
                for (int h = 0; h < 2; ++h) {
                    int row = wm * 32 + ti * 16 + h * 8 + lr;
#pragma unroll
                    for (int c = 0; c < 3; ++c)
                        sp[(wn * 128 + row) * 3 + c] = part[ti][h][c];
                }
        }
        __syncthreads();
        for (int i = tid; i < 384; i += 256) {
            float v = sp[i] + sp[384 + i];
            atomicAdd(&g_PRED[(size_t)(m0 + i / 3) * 3 + (i % 3)], v);
        }
    }
}

// ---------------- output combine --------------------------------------------
__global__ __launch_bounds__(256)
void out_combine(const float* __restrict__ b5, float* __restrict__ out) {
    int q = blockIdx.x * 256 + threadIdx.x;
    float ar[4], tot = 0.f;
#pragma unroll
    for (int s = 0; s < 4; ++s) { ar[s] = g_AREA[(size_t)s * Q + q]; tot += ar[s]; }
    float r0 = 0.f, r1 = 0.f, r2 = 0.f;
#pragma unroll
    for (int s = 0; s < 4; ++s) {
        float wgt = ar[3 - s] / tot;
        size_t base = ((size_t)s * Q + q) * 3;
        r0 += (g_PRED[base + 0] + b5[0]) * wgt;
        r1 += (g_PRED[base + 1] + b5[1]) * wgt;
        r2 += (g_PRED[base + 2] + b5[2]) * wgt;
    }
    out[(size_t)q * 3 + 0] = r0;
    out[(size_t)q * 3 + 1] = r1;
    out[(size_t)q * 3 + 2] = r2;
}

// ---------------- launch ----------------------------------------------------
extern "C" void kernel_launch(void* const* d_in, const int* in_sizes, int n_in,
                              void* d_out, int out_size) {
    const float* F    = (const float*)d_in[0];
    const float* loc  = (const float*)d_in[1];
    const float* cell = (const float*)d_in[2];
    const float* w1 = (const float*)d_in[3];
    const float* b1 = (const float*)d_in[4];
    const float* w2 = (const float*)d_in[5];
    const float* b2 = (const float*)d_in[6];
    const float* w3 = (const float*)d_in[7];
    const float* b3 = (const float*)d_in[8];
    const float* w4 = (const float*)d_in[9];
    const float* b4 = (const float*)d_in[10];
    const float* w5 = (const float*)d_in[11];
    const float* b5 = (const float*)d_in[12];
    float* out = (float*)d_out;

    __nv_bfloat16 *XCh, *XCl, *HAh, *HAl, *HBh, *HBl;
    __nv_bfloat16 *W1h, *W1l, *W2h, *W2l, *W3h, *W3l, *W4h, *W4l;
    float *G, *PRED;
    cudaGetSymbolAddress((void**)&XCh, g_XCh); cudaGetSymbolAddress((void**)&XCl, g_XCl);
    cudaGetSymbolAddress((void**)&G,   g_G);
    cudaGetSymbolAddress((void**)&PRED, g_PRED);
    cudaGetSymbolAddress((void**)&HAh, g_HAh); cudaGetSymbolAddress((void**)&HAl, g_HAl);
    cudaGetSymbolAddress((void**)&HBh, g_HBh); cudaGetSymbolAddress((void**)&HBl, g_HBl);
    cudaGetSymbolAddress((void**)&W1h, g_W1h); cudaGetSymbolAddress((void**)&W1l, g_W1l);
    cudaGetSymbolAddress((void**)&W2h, g_W2h); cudaGetSymbolAddress((void**)&W2l, g_W2l);
    cudaGetSymbolAddress((void**)&W3h, g_W3h); cudaGetSymbolAddress((void**)&W3l, g_W3l);
    cudaGetSymbolAddress((void**)&W4h, g_W4h); cudaGetSymbolAddress((void**)&W4l, g_W4l);

    cudaFuncSetAttribute(hmma_gemm<KC, 0>,
        cudaFuncAttributeMaxDynamicSharedMemorySize, SMEMB);
    cudaFuncSetAttribute(hmma_gemm<256, 1>,
        cudaFuncAttributeMaxDynamicSharedMemorySize, SMEMB);
    cudaFuncSetAttribute(hmma_gemm<256, 2>,
        cudaFuncAttributeMaxDynamicSharedMemorySize, SMEMB);

    prep_w_kernel<<<(256 * KC  + 255) / 256, 256>>>(w1, KC,  KC,  W1h, W1l);
    prep_w_kernel<<<(256 * 256 + 255) / 256, 256>>>(w2, 256, 256, W2h, W2l);
    prep_w_kernel<<<(256 * 256 + 255) / 256, 256>>>(w3, 256, 256, W3h, W3l);
    prep_w_kernel<<<(256 * 256 + 255) / 256, 256>>>(w4, 256, 256, W4h, W4l);

    im2col_kernel<<<NPIX, KC>>>(F);

    // conv GEMM: G[65536,256] = XC @ W1[0:288]^T
    hmma_gemm<KC, 0><<<dim3(NPIX / 128, 2), 256, SMEMB>>>(
        XCh, XCl, W1h, W1l, nullptr, G, nullptr, nullptr);

    combine_kernel<<<dim3(Q, 4), 128>>>(loc, cell, w1, b1, HAh, HAl);

    cudaMemsetAsync(PRED, 0, (size_t)MROWS * 3 * sizeof(float));

    dim3 ggrid(MROWS / 128, 2);
    hmma_gemm<256, 1><<<ggrid, 256, SMEMB>>>(HAh, HAl, W2h, W2l, b2, HBh, HBl, nullptr);
    hmma_gemm<256, 1><<<ggrid, 256, SMEMB>>>(HBh, HBl, W3h, W3l, b3, HAh, HAl, nullptr);
    hmma_gemm<256, 2><<<ggrid, 256, SMEMB>>>(HAh, HAl, W4h, W4l, b4, nullptr, nullptr, w5);

    out_combine<<<Q / 256, 256>>>(b5, out);
}

// round 9
// speedup vs baseline: 1.6849x; 1.0218x over previous
#include <cuda_runtime.h>
#include <cuda_bf16.h>
#include <cstdint>

#define Q     65536
#define HH    256
#define WW    256
#define NPIX  (HH*WW)    /* 65536 */
#define MROWS (4*Q)      /* 262144 */
#define KC    288        /* conv GEMM K: 9 stages of 32 */
#define NHID  256

typedef unsigned int u32;

// ---------------- scratch (device globals; no allocation allowed) ----------
__device__ __nv_bfloat16 g_XCh[(size_t)NPIX * KC];
__device__ __nv_bfloat16 g_XCl[(size_t)NPIX * KC];
__device__ float         g_G  [(size_t)NPIX * NHID];
__device__ __nv_bfloat16 g_HAh[(size_t)MROWS * NHID];
__device__ __nv_bfloat16 g_HAl[(size_t)MROWS * NHID];
__device__ __nv_bfloat16 g_HBh[(size_t)MROWS * NHID];
__device__ __nv_bfloat16 g_HBl[(size_t)MROWS * NHID];
__device__ float g_PRED[(size_t)MROWS * 3];
__device__ float g_AREA[MROWS];
__device__ __nv_bfloat16 g_W1h[256 * KC],  g_W1l[256 * KC];
__device__ __nv_bfloat16 g_W2h[256 * 256], g_W2l[256 * 256];
__device__ __nv_bfloat16 g_W3h[256 * 256], g_W3l[256 * 256];
__device__ __nv_bfloat16 g_W4h[256 * 256], g_W4l[256 * 256];

// ---------------- helpers ---------------------------------------------------
__device__ __forceinline__ u32 pack2(float x, float y) {
    __nv_bfloat162 t = __floats2bfloat162_rn(x, y);
    return *reinterpret_cast<u32*>(&t);
}
__device__ __forceinline__ void mma_bf16(float* d, const u32* a, const u32* b) {
    asm("mma.sync.aligned.m16n8k16.row.col.f32.bf16.bf16.f32 "
        "{%0,%1,%2,%3}, {%4,%5,%6,%7}, {%8,%9}, {%0,%1,%2,%3};"
        : "+f"(d[0]), "+f"(d[1]), "+f"(d[2]), "+f"(d[3])
        : "r"(a[0]), "r"(a[1]), "r"(a[2]), "r"(a[3]), "r"(b[0]), "r"(b[1]));
}
__device__ __forceinline__ void ldsm4(u32* r, const __nv_bfloat16* p) {
    u32 a = (u32)__cvta_generic_to_shared(p);
    asm volatile("ldmatrix.sync.aligned.m8n8.x4.shared.b16 {%0,%1,%2,%3}, [%4];"
                 : "=r"(r[0]), "=r"(r[1]), "=r"(r[2]), "=r"(r[3]) : "r"(a));
}
__device__ __forceinline__ void cp16(__nv_bfloat16* s, const __nv_bfloat16* g) {
    u32 sa = (u32)__cvta_generic_to_shared(s);
    asm volatile("cp.async.cg.shared.global [%0], [%1], 16;" :: "r"(sa), "l"(g));
}
__device__ __forceinline__ void cp_commit() {
    asm volatile("cp.async.commit_group;" ::: "memory");
}
template<int N> __device__ __forceinline__ void cp_wait() {
    asm volatile("cp.async.wait_group %0;" :: "n"(N) : "memory");
}

// ---------------- W prep (all 4 weights in ONE launch) ----------------------
// segment layout: w1 -> 256*288 elems, then w2,w3,w4 -> 256*256 each
__global__ void prep_all_kernel(const float* __restrict__ w1,
                                const float* __restrict__ w2,
                                const float* __restrict__ w3,
                                const float* __restrict__ w4) {
    int i = blockIdx.x * 256 + threadIdx.x;
    const int S1 = 256 * KC;
    const int S  = 256 * 256;
    const float* w;
    __nv_bfloat16 *hi, *lo;
    int Kpad, idx;
    if (i < S1)              { w = w1; hi = g_W1h; lo = g_W1l; Kpad = KC;  idx = i; }
    else if (i < S1 + S)     { w = w2; hi = g_W2h; lo = g_W2l; Kpad = 256; idx = i - S1; }
    else if (i < S1 + 2 * S) { w = w3; hi = g_W3h; lo = g_W3l; Kpad = 256; idx = i - S1 - S; }
    else if (i < S1 + 3 * S) { w = w4; hi = g_W4h; lo = g_W4l; Kpad = 256; idx = i - S1 - 2 * S; }
    else return;
    int n = idx / Kpad, k = idx - n * Kpad;
    float v = w[(size_t)k * 256 + n];
    __nv_bfloat16 h = __float2bfloat16(v);
    hi[idx] = h;
    lo[idx] = __float2bfloat16(v - __bfloat162float(h));
}

// ---------------- im2col: per-pixel 3x3 reflect patch -> bf16 hi/lo --------
__global__ void im2col_kernel(const float* __restrict__ F) {
    const int p = blockIdx.x;
    const int t = threadIdx.x;         // 0..287
    const int y0 = p >> 8, x0 = p & 255;
    int c  = t / 9;
    int k  = t - c * 9;
    int di = k / 3, dj = k - di * 3;
    int y = y0 + di - 1;
    int x = x0 + dj - 1;
    y = (y < 0) ? -y : ((y >= HH) ? 2 * HH - 2 - y : y);
    x = (x < 0) ? -x : ((x >= WW) ? 2 * WW - 2 - x : x);
    float v = F[(size_t)c * NPIX + y * WW + x];
    __nv_bfloat16 h = __float2bfloat16(v);
    g_XCh[(size_t)p * KC + t] = h;
    g_XCl[(size_t)p * KC + t] = __float2bfloat16(v - __bfloat162float(h));
}

// ---------------- combine: H1 = relu(G[p] + rel/cell terms + b1) -----------
__global__ __launch_bounds__(128)
void combine_kernel(const float* __restrict__ loc,
                    const float* __restrict__ cell,
                    const float* __restrict__ w1,
                    const float* __restrict__ b1,
                    __nv_bfloat16* __restrict__ Hh,
                    __nv_bfloat16* __restrict__ Hl) {
    const int q = blockIdx.x;
    const int s = blockIdx.y;
    const int t = threadIdx.x;

    float l0 = loc[(size_t)q * 2 + 0];
    float l1 = loc[(size_t)q * 2 + 1];
    float sy = (s & 2) ? 1.f : -1.f;
    float sx = (s & 1) ? 1.f : -1.f;
    float ly = l0 + sy * (1.f / HH) + 1e-6f;
    float lx = l1 + sx * (1.f / WW) + 1e-6f;
    ly = fminf(fmaxf(ly, -1.f + 1e-6f), 1.f - 1e-6f);
    lx = fminf(fmaxf(lx, -1.f + 1e-6f), 1.f - 1e-6f);
    int iy = (int)rintf(((ly + 1.f) * HH - 1.f) * 0.5f);
    int ix = (int)rintf(((lx + 1.f) * WW - 1.f) * 0.5f);
    iy = min(max(iy, 0), HH - 1);
    ix = min(max(ix, 0), WW - 1);
    float qy = -1.f + (2.f * iy + 1.f) / HH;
    float qx = -1.f + (2.f * ix + 1.f) / WW;
    float rel0 = (l0 - qy) * HH;
    float rel1 = (l1 - qx) * WW;
    float c0 = cell[(size_t)q * 2 + 0] * HH;
    float c1 = cell[(size_t)q * 2 + 1] * WW;

    const size_t row = (size_t)s * Q + q;
    const int p = iy * WW + ix;
    if (t == 0) g_AREA[row] = fabsf(rel0 * rel1) + 1e-9f;

    const float2* gg  = reinterpret_cast<const float2*>(g_G + (size_t)p * NHID);
    const float2* wr0 = reinterpret_cast<const float2*>(w1 + 288 * 256);
    const float2* wr1 = wr0 + 128;
    const float2* wr2 = wr1 + 128;
    const float2* wr3 = wr2 + 128;
    const float2* bb  = reinterpret_cast<const float2*>(b1);

    float2 g  = gg[t];
    float2 a0 = wr0[t], a1 = wr1[t], a2 = wr2[t], a3 = wr3[t];
    float2 bv = bb[t];
    float v0 = g.x + rel0 * a0.x + rel1 * a1.x + c0 * a2.x + c1 * a3.x + bv.x;
    float v1 = g.y + rel0 * a0.y + rel1 * a1.y + c0 * a2.y + c1 * a3.y + bv.y;
    v0 = fmaxf(v0, 0.f); v1 = fmaxf(v1, 0.f);
    float h0 = __bfloat162float(__float2bfloat16(v0));
    float h1 = __bfloat162float(__float2bfloat16(v1));
    size_t off = row * NHID + t * 2;
    *reinterpret_cast<u32*>(Hh + off) = pack2(h0, h1);
    *reinterpret_cast<u32*>(Hl + off) = pack2(v0 - h0, v1 - h1);
}

// ---------------- HMMA bf16-3x GEMM, 128x128 tile ---------------------------
// grid = (2, M/128): the two n-CTAs sharing an A row-block are ADJACENT
#define SST    40
#define PLANE  (128 * SST)
#define STAGE  (4 * PLANE)     /* Ah,Al,Bh,Bl */
#define SMEMB  (2 * STAGE * 2) /* 81920 B */

template<int K>
__device__ __forceinline__ void load_stage(
        __nv_bfloat16* st,
        const __nv_bfloat16* __restrict__ Ah, const __nv_bfloat16* __restrict__ Al,
        const __nv_bfloat16* __restrict__ Bh, const __nv_bfloat16* __restrict__ Bl,
        int m0, int n0, int kb, int tid) {
#pragma unroll
    for (int i = 0; i < 2; ++i) {
        int chunk = tid + i * 256;
        int row = chunk >> 2;
        int c8  = (chunk & 3) << 3;
        size_t ga = (size_t)(m0 + row) * K + kb + c8;
        size_t gb = (size_t)(n0 + row) * K + kb + c8;
        int so = row * SST + c8;
        cp16(st + so,             Ah + ga);
        cp16(st + PLANE + so,     Al + ga);
        cp16(st + 2 * PLANE + so, Bh + gb);
        cp16(st + 3 * PLANE + so, Bl + gb);
    }
}

// MODE: 0 = fp32 raw out; 1 = bias+relu -> bf16 hi/lo; 2 = bias+relu -> dot w5 -> atomicAdd
template<int K, int MODE>
__global__ __launch_bounds__(256, 2)
void hmma_gemm(const __nv_bfloat16* __restrict__ Ah,
               const __nv_bfloat16* __restrict__ Al,
               const __nv_bfloat16* __restrict__ Bh,
               const __nv_bfloat16* __restrict__ Bl,
               const float* __restrict__ bias,
               void* __restrict__ Cout,
               __nv_bfloat16* __restrict__ Clo,
               const float* __restrict__ w5) {
    extern __shared__ __nv_bfloat16 smem[];

    const int tid  = threadIdx.x;
    const int lane = tid & 31;
    const int wid  = tid >> 5;
    const int wm   = wid & 3;
    const int wn   = wid >> 2;
    const int m0   = blockIdx.y * 128;      // swapped: y = m-block
    const int n0   = blockIdx.x * 128;      //          x = n-block (adjacent pair)
    const int lr   = lane >> 2;
    const int lq   = lane & 3;
    const int grp  = lane >> 3;
    const int rr   = lane & 7;

    const int a_row = wm * 32 + (grp & 1) * 8 + rr;
    const int a_kb  = (grp >> 1) * 8;
    const int b_row = wn * 64 + (grp >> 1) * 8 + rr;
    const int b_kb  = (grp & 1) * 8;

    float acc[2][8][4];
#pragma unroll
    for (int i = 0; i < 2; ++i)
#pragma unroll
        for (int j = 0; j < 8; ++j)
#pragma unroll
            for (int c = 0; c < 4; ++c) acc[i][j][c] = 0.f;

    constexpr int S = K / 32;
    load_stage<K>(smem, Ah, Al, Bh, Bl, m0, n0, 0, tid);
    cp_commit();

    for (int s = 0; s < S; ++s) {
        if (s + 1 < S) {
            load_stage<K>(smem + ((s + 1) & 1) * STAGE, Ah, Al, Bh, Bl,
                          m0, n0, (s + 1) * 32, tid);
            cp_commit();
            cp_wait<1>();
        } else {
            cp_wait<0>();
        }
        __syncthreads();

        const __nv_bfloat16* sAh = smem + (s & 1) * STAGE;
        const __nv_bfloat16* sAl = sAh + PLANE;
        const __nv_bfloat16* sBh = sAh + 2 * PLANE;
        const __nv_bfloat16* sBl = sAh + 3 * PLANE;

#pragma unroll
        for (int ks = 0; ks < 32; ks += 16) {
            u32 af[2][2][4];
#pragma unroll
            for (int ti = 0; ti < 2; ++ti) {
                ldsm4(af[ti][0], sAh + (a_row + ti * 16) * SST + ks + a_kb);
                ldsm4(af[ti][1], sAl + (a_row + ti * 16) * SST + ks + a_kb);
            }
#pragma unroll
            for (int jp = 0; jp < 4; ++jp) {
                u32 bh[4], bl[4];
                ldsm4(bh, sBh + (b_row + jp * 16) * SST + ks + b_kb);
                ldsm4(bl, sBl + (b_row + jp * 16) * SST + ks + b_kb);
#pragma unroll
                for (int ti = 0; ti < 2; ++ti) {
                    mma_bf16(acc[ti][2 * jp],     af[ti][0], bh);
                    mma_bf16(acc[ti][2 * jp],     af[ti][0], bl);
                    mma_bf16(acc[ti][2 * jp],     af[ti][1], bh);
                    mma_bf16(acc[ti][2 * jp + 1], af[ti][0], bh + 2);
                    mma_bf16(acc[ti][2 * jp + 1], af[ti][0], bl + 2);
                    mma_bf16(acc[ti][2 * jp + 1], af[ti][1], bh + 2);
                }
            }
        }
        __syncthreads();
    }

    // ---- epilogue ----
    if (MODE == 0) {
        float* C = (float*)Cout;
#pragma unroll
        for (int ti = 0; ti < 2; ++ti) {
            int row0 = m0 + wm * 32 + ti * 16 + lr;
#pragma unroll
            for (int tj = 0; tj < 8; ++tj) {
                int col0 = n0 + wn * 64 + tj * 8 + lq * 2;
#pragma unroll
                for (int half = 0; half < 2; ++half) {
                    size_t off = (size_t)(row0 + half * 8) * NHID + col0;
                    *reinterpret_cast<float2*>(C + off) =
                        make_float2(acc[ti][tj][half * 2 + 0],
                                    acc[ti][tj][half * 2 + 1]);
                }
            }
        }
    } else if (MODE == 1) {
        __nv_bfloat16* Chi = (__nv_bfloat16*)Cout;
#pragma unroll
        for (int ti = 0; ti < 2; ++ti) {
            int row0 = m0 + wm * 32 + ti * 16 + lr;
#pragma unroll
            for (int tj = 0; tj < 8; ++tj) {
                int col0 = n0 + wn * 64 + tj * 8 + lq * 2;
                float b0 = bias[col0], b1 = bias[col0 + 1];
#pragma unroll
                for (int half = 0; half < 2; ++half) {
                    size_t off = (size_t)(row0 + half * 8) * NHID + col0;
                    float v0 = fmaxf(acc[ti][tj][half * 2 + 0] + b0, 0.f);
                    float v1 = fmaxf(acc[ti][tj][half * 2 + 1] + b1, 0.f);
                    float h0 = __bfloat162float(__float2bfloat16(v0));
                    float h1 = __bfloat162float(__float2bfloat16(v1));
                    *reinterpret_cast<u32*>(Chi + off) = pack2(h0, h1);
                    *reinterpret_cast<u32*>(Clo + off) = pack2(v0 - h0, v1 - h1);
                }
            }
        }
    } else {
        // MODE 2: bias + relu + dot with w5[256][3] -> g_PRED (atomicAdd over 2 n-CTAs)
        float part[2][2][3];
#pragma unroll
        for (int ti = 0; ti < 2; ++ti)
#pragma unroll
            for (int h = 0; h < 2; ++h)
#pragma unroll
                for (int c = 0; c < 3; ++c) part[ti][h][c] = 0.f;

#pragma unroll
        for (int tj = 0; tj < 8; ++tj) {
            int col0 = n0 + wn * 64 + tj * 8 + lq * 2;
            float b0 = bias[col0], b1 = bias[col0 + 1];
            float w50[3], w51[3];
#pragma unroll
            for (int c = 0; c < 3; ++c) {
                w50[c] = w5[col0 * 3 + c];
                w51[c] = w5[(col0 + 1) * 3 + c];
            }
#pragma unroll
            for (int ti = 0; ti < 2; ++ti)
#pragma unroll
                for (int half = 0; half < 2; ++half) {
                    float v0 = fmaxf(acc[ti][tj][half * 2 + 0] + b0, 0.f);
                    float v1 = fmaxf(acc[ti][tj][half * 2 + 1] + b1, 0.f);
#pragma unroll
                    for (int c = 0; c < 3; ++c)
                        part[ti][half][c] += v0 * w50[c] + v1 * w51[c];
                }
        }
#pragma unroll
        for (int ti = 0; ti < 2; ++ti)
#pragma unroll
            for (int h = 0; h < 2; ++h)
#pragma unroll
                for (int c = 0; c < 3; ++c) {
                    float v = part[ti][h][c];
                    v += __shfl_xor_sync(0xffffffffu, v, 1);
                    v += __shfl_xor_sync(0xffffffffu, v, 2);
                    part[ti][h][c] = v;
                }
        float* sp = reinterpret_cast<float*>(smem);   // [2][128][3] = 768 floats
        if (lq == 0) {
#pragma unroll
            for (int ti = 0; ti < 2; ++ti)
#pragma unroll
                for (int h = 0; h < 2; ++h) {
                    int row = wm * 32 + ti * 16 + h * 8 + lr;
#pragma unroll
                    for (int c = 0; c < 3; ++c)
                        sp[(wn * 128 + row) * 3 + c] = part[ti][h][c];
                }
        }
        __syncthreads();
        for (int i = tid; i < 384; i += 256) {
            float v = sp[i] + sp[384 + i];
            atomicAdd(&g_PRED[(size_t)(m0 + i / 3) * 3 + (i % 3)], v);
        }
    }
}

// ---------------- output combine --------------------------------------------
__global__ __launch_bounds__(256)
void out_combine(const float* __restrict__ b5, float* __restrict__ out) {
    int q = blockIdx.x * 256 + threadIdx.x;
    float ar[4], tot = 0.f;
#pragma unroll
    for (int s = 0; s < 4; ++s) { ar[s] = g_AREA[(size_t)s * Q + q]; tot += ar[s]; }
    float r0 = 0.f, r1 = 0.f, r2 = 0.f;
#pragma unroll
    for (int s = 0; s < 4; ++s) {
        float wgt = ar[3 - s] / tot;
        size_t base = ((size_t)s * Q + q) * 3;
        r0 += (g_PRED[base + 0] + b5[0]) * wgt;
        r1 += (g_PRED[base + 1] + b5[1]) * wgt;
        r2 += (g_PRED[base + 2] + b5[2]) * wgt;
    }
    out[(size_t)q * 3 + 0] = r0;
    out[(size_t)q * 3 + 1] = r1;
    out[(size_t)q * 3 + 2] = r2;
}

// ---------------- launch ----------------------------------------------------
extern "C" void kernel_launch(void* const* d_in, const int* in_sizes, int n_in,
                              void* d_out, int out_size) {
    const float* F    = (const float*)d_in[0];
    const float* loc  = (const float*)d_in[1];
    const float* cell = (const float*)d_in[2];
    const float* w1 = (const float*)d_in[3];
    const float* b1 = (const float*)d_in[4];
    const float* w2 = (const float*)d_in[5];
    const float* b2 = (const float*)d_in[6];
    const float* w3 = (const float*)d_in[7];
    const float* b3 = (const float*)d_in[8];
    const float* w4 = (const float*)d_in[9];
    const float* b4 = (const float*)d_in[10];
    const float* w5 = (const float*)d_in[11];
    const float* b5 = (const float*)d_in[12];
    float* out = (float*)d_out;

    __nv_bfloat16 *XCh, *XCl, *HAh, *HAl, *HBh, *HBl;
    __nv_bfloat16 *W1h, *W1l, *W2h, *W2l, *W3h, *W3l, *W4h, *W4l;
    float *G, *PRED;
    cudaGetSymbolAddress((void**)&XCh, g_XCh); cudaGetSymbolAddress((void**)&XCl, g_XCl);
    cudaGetSymbolAddress((void**)&G,   g_G);
    cudaGetSymbolAddress((void**)&PRED, g_PRED);
    cudaGetSymbolAddress((void**)&HAh, g_HAh); cudaGetSymbolAddress((void**)&HAl, g_HAl);
    cudaGetSymbolAddress((void**)&HBh, g_HBh); cudaGetSymbolAddress((void**)&HBl, g_HBl);
    cudaGetSymbolAddress((void**)&W1h, g_W1h); cudaGetSymbolAddress((void**)&W1l, g_W1l);
    cudaGetSymbolAddress((void**)&W2h, g_W2h); cudaGetSymbolAddress((void**)&W2l, g_W2l);
    cudaGetSymbolAddress((void**)&W3h, g_W3h); cudaGetSymbolAddress((void**)&W3l, g_W3l);
    cudaGetSymbolAddress((void**)&W4h, g_W4h); cudaGetSymbolAddress((void**)&W4l, g_W4l);

    cudaFuncSetAttribute(hmma_gemm<KC, 0>,
        cudaFuncAttributeMaxDynamicSharedMemorySize, SMEMB);
    cudaFuncSetAttribute(hmma_gemm<256, 1>,
        cudaFuncAttributeMaxDynamicSharedMemorySize, SMEMB);
    cudaFuncSetAttribute(hmma_gemm<256, 2>,
        cudaFuncAttributeMaxDynamicSharedMemorySize, SMEMB);

    cudaMemsetAsync(PRED, 0, (size_t)MROWS * 3 * sizeof(float));

    const int PREP_ELEMS = 256 * KC + 3 * 256 * 256;
    prep_all_kernel<<<(PREP_ELEMS + 255) / 256, 256>>>(w1, w2, w3, w4);

    im2col_kernel<<<NPIX, KC>>>(F);

    // conv GEMM: G[65536,256] = XC @ W1[0:288]^T   (grid: n-pair adjacent)
    hmma_gemm<KC, 0><<<dim3(2, NPIX / 128), 256, SMEMB>>>(
        XCh, XCl, W1h, W1l, nullptr, G, nullptr, nullptr);

    combine_kernel<<<dim3(Q, 4), 128>>>(loc, cell, w1, b1, HAh, HAl);

    dim3 ggrid(2, MROWS / 128);
    hmma_gemm<256, 1><<<ggrid, 256, SMEMB>>>(HAh, HAl, W2h, W2l, b2, HBh, HBl, nullptr);
    hmma_gemm<256, 1><<<ggrid, 256, SMEMB>>>(HBh, HBl, W3h, W3l, b3, HAh, HAl, nullptr);
    hmma_gemm<256, 2><<<ggrid, 256, SMEMB>>>(HAh, HAl, W4h, W4l, b4, nullptr, nullptr, w5);

    out_combine<<<Q / 256, 256>>>(b5, out);
}

// round 10
// speedup vs baseline: 1.7138x; 1.0172x over previous
#include <cuda_runtime.h>
#include <cuda_bf16.h>
#include <cstdint>

#define Q     65536
#define HH    256
#define WW    256
#define NPIX  (HH*WW)    /* 65536 */
#define MROWS (4*Q)      /* 262144 */
#define KC    288        /* conv GEMM K: 9 stages of 32 */
#define NHID  256

typedef unsigned int u32;

// ---------------- scratch (device globals; no allocation allowed) ----------
__device__ __nv_bfloat16 g_XCh[(size_t)NPIX * KC];
__device__ __nv_bfloat16 g_XCl[(size_t)NPIX * KC];
__device__ float         g_G  [(size_t)NPIX * NHID];
__device__ __nv_bfloat16 g_HAh[(size_t)MROWS * NHID];
__device__ __nv_bfloat16 g_HAl[(size_t)MROWS * NHID];
__device__ __nv_bfloat16 g_HBh[(size_t)MROWS * NHID];
__device__ __nv_bfloat16 g_HBl[(size_t)MROWS * NHID];
__device__ float g_PRED[(size_t)MROWS * 3];
__device__ float g_AREA[MROWS];
__device__ int    g_RIP[MROWS];         // pixel index per row
__device__ float4 g_RIV[MROWS];         // rel0, rel1, c0, c1
__device__ __nv_bfloat16 g_W1h[256 * KC],  g_W1l[256 * KC];
__device__ __nv_bfloat16 g_W2h[256 * 256], g_W2l[256 * 256];
__device__ __nv_bfloat16 g_W3h[256 * 256], g_W3l[256 * 256];
__device__ __nv_bfloat16 g_W4h[256 * 256], g_W4l[256 * 256];

// ---------------- helpers ---------------------------------------------------
__device__ __forceinline__ u32 pack2(float x, float y) {
    __nv_bfloat162 t = __floats2bfloat162_rn(x, y);
    return *reinterpret_cast<u32*>(&t);
}
__device__ __forceinline__ void mma_bf16(float* d, const u32* a, const u32* b) {
    asm("mma.sync.aligned.m16n8k16.row.col.f32.bf16.bf16.f32 "
        "{%0,%1,%2,%3}, {%4,%5,%6,%7}, {%8,%9}, {%0,%1,%2,%3};"
        : "+f"(d[0]), "+f"(d[1]), "+f"(d[2]), "+f"(d[3])
        : "r"(a[0]), "r"(a[1]), "r"(a[2]), "r"(a[3]), "r"(b[0]), "r"(b[1]));
}
__device__ __forceinline__ void ldsm4(u32* r, const __nv_bfloat16* p) {
    u32 a = (u32)__cvta_generic_to_shared(p);
    asm volatile("ldmatrix.sync.aligned.m8n8.x4.shared.b16 {%0,%1,%2,%3}, [%4];"
                 : "=r"(r[0]), "=r"(r[1]), "=r"(r[2]), "=r"(r[3]) : "r"(a));
}
__device__ __forceinline__ void cp16(__nv_bfloat16* s, const __nv_bfloat16* g) {
    u32 sa = (u32)__cvta_generic_to_shared(s);
    asm volatile("cp.async.cg.shared.global [%0], [%1], 16;" :: "r"(sa), "l"(g));
}
__device__ __forceinline__ void cp_commit() {
    asm volatile("cp.async.commit_group;" ::: "memory");
}
template<int N> __device__ __forceinline__ void cp_wait() {
    asm volatile("cp.async.wait_group %0;" :: "n"(N) : "memory");
}

// ---------------- W prep (all 4 weights in ONE launch) ----------------------
__global__ void prep_all_kernel(const float* __restrict__ w1,
                                const float* __restrict__ w2,
                                const float* __restrict__ w3,
                                const float* __restrict__ w4) {
    int i = blockIdx.x * 256 + threadIdx.x;
    const int S1 = 256 * KC;
    const int S  = 256 * 256;
    const float* w;
    __nv_bfloat16 *hi, *lo;
    int Kpad, idx;
    if (i < S1)              { w = w1; hi = g_W1h; lo = g_W1l; Kpad = KC;  idx = i; }
    else if (i < S1 + S)     { w = w2; hi = g_W2h; lo = g_W2l; Kpad = 256; idx = i - S1; }
    else if (i < S1 + 2 * S) { w = w3; hi = g_W3h; lo = g_W3l; Kpad = 256; idx = i - S1 - S; }
    else if (i < S1 + 3 * S) { w = w4; hi = g_W4h; lo = g_W4l; Kpad = 256; idx = i - S1 - 2 * S; }
    else return;
    int n = idx / Kpad, k = idx - n * Kpad;
    float v = w[(size_t)k * 256 + n];
    __nv_bfloat16 h = __float2bfloat16(v);
    hi[idx] = h;
    lo[idx] = __float2bfloat16(v - __bfloat162float(h));
}

// ---------------- im2col: per-pixel 3x3 reflect patch -> bf16 hi/lo --------
__global__ void im2col_kernel(const float* __restrict__ F) {
    const int p = blockIdx.x;
    const int t = threadIdx.x;         // 0..287
    const int y0 = p >> 8, x0 = p & 255;
    int c  = t / 9;
    int k  = t - c * 9;
    int di = k / 3, dj = k - di * 3;
    int y = y0 + di - 1;
    int x = x0 + dj - 1;
    y = (y < 0) ? -y : ((y >= HH) ? 2 * HH - 2 - y : y);
    x = (x < 0) ? -x : ((x >= WW) ? 2 * WW - 2 - x : x);
    float v = F[(size_t)c * NPIX + y * WW + x];
    __nv_bfloat16 h = __float2bfloat16(v);
    g_XCh[(size_t)p * KC + t] = h;
    g_XCl[(size_t)p * KC + t] = __float2bfloat16(v - __bfloat162float(h));
}

// ---------------- rowinfo: per-(q,s) scalars, once -------------------------
__global__ __launch_bounds__(256)
void rowinfo_kernel(const float* __restrict__ loc,
                    const float* __restrict__ cell) {
    int i = blockIdx.x * 256 + threadIdx.x;   // row = s*Q + q
    int q = i & (Q - 1);
    int s = i >> 16;

    float l0 = loc[(size_t)q * 2 + 0];
    float l1 = loc[(size_t)q * 2 + 1];
    float sy = (s & 2) ? 1.f : -1.f;
    float sx = (s & 1) ? 1.f : -1.f;
    float ly = l0 + sy * (1.f / HH) + 1e-6f;
    float lx = l1 + sx * (1.f / WW) + 1e-6f;
    ly = fminf(fmaxf(ly, -1.f + 1e-6f), 1.f - 1e-6f);
    lx = fminf(fmaxf(lx, -1.f + 1e-6f), 1.f - 1e-6f);
    int iy = (int)rintf(((ly + 1.f) * HH - 1.f) * 0.5f);
    int ix = (int)rintf(((lx + 1.f) * WW - 1.f) * 0.5f);
    iy = min(max(iy, 0), HH - 1);
    ix = min(max(ix, 0), WW - 1);
    float qy = -1.f + (2.f * iy + 1.f) / HH;
    float qx = -1.f + (2.f * ix + 1.f) / WW;
    float rel0 = (l0 - qy) * HH;
    float rel1 = (l1 - qx) * WW;
    float c0 = cell[(size_t)q * 2 + 0] * HH;
    float c1 = cell[(size_t)q * 2 + 1] * WW;

    g_RIP[i]  = iy * WW + ix;
    g_RIV[i]  = make_float4(rel0, rel1, c0, c1);
    g_AREA[i] = fabsf(rel0 * rel1) + 1e-9f;
}

// ---------------- combine2: H1 = relu(G[p] + rank-4 + b1) -> bf16 hi/lo ----
__global__ __launch_bounds__(256)
void combine2_kernel(const float* __restrict__ w1,
                     const float* __restrict__ b1,
                     __nv_bfloat16* __restrict__ Hh,
                     __nv_bfloat16* __restrict__ Hl) {
    __shared__ float sw[5 * 256];   // w1 rows 288..291, then b1
    const int tid = threadIdx.x;
    for (int i = tid; i < 1024; i += 256) sw[i] = w1[288 * 256 + i];
    if (tid < 256) sw[1024 + tid] = b1[tid];
    __syncthreads();

    const size_t row = (size_t)blockIdx.x * 4 + (tid >> 6);
    const int c4 = (tid & 63) * 4;

    const int p = g_RIP[row];
    const float4 rc = g_RIV[row];

    float4 g  = *reinterpret_cast<const float4*>(g_G + (size_t)p * NHID + c4);
    float4 wA = *reinterpret_cast<const float4*>(sw + c4);          // row 288
    float4 wB = *reinterpret_cast<const float4*>(sw + 256 + c4);    // row 289
    float4 wC = *reinterpret_cast<const float4*>(sw + 512 + c4);    // row 290
    float4 wD = *reinterpret_cast<const float4*>(sw + 768 + c4);    // row 291
    float4 bb = *reinterpret_cast<const float4*>(sw + 1024 + c4);

    float v[4];
    v[0] = fmaxf(g.x + rc.x * wA.x + rc.y * wB.x + rc.z * wC.x + rc.w * wD.x + bb.x, 0.f);
    v[1] = fmaxf(g.y + rc.x * wA.y + rc.y * wB.y + rc.z * wC.y + rc.w * wD.y + bb.y, 0.f);
    v[2] = fmaxf(g.z + rc.x * wA.z + rc.y * wB.z + rc.z * wC.z + rc.w * wD.z + bb.z, 0.f);
    v[3] = fmaxf(g.w + rc.x * wA.w + rc.y * wB.w + rc.z * wC.w + rc.w * wD.w + bb.w, 0.f);

    float h[4];
#pragma unroll
    for (int j = 0; j < 4; ++j) h[j] = __bfloat162float(__float2bfloat16(v[j]));

    size_t off = row * NHID + c4;
    *reinterpret_cast<uint2*>(Hh + off) = make_uint2(pack2(h[0], h[1]), pack2(h[2], h[3]));
    *reinterpret_cast<uint2*>(Hl + off) = make_uint2(pack2(v[0] - h[0], v[1] - h[1]),
                                                     pack2(v[2] - h[2], v[3] - h[3]));
}

// ---------------- HMMA bf16-3x GEMM, 128x128 tile ---------------------------
#define SST    40
#define PLANE  (128 * SST)
#define STAGE  (4 * PLANE)     /* Ah,Al,Bh,Bl */
#define SMEMB  (2 * STAGE * 2) /* 81920 B */

template<int K>
__device__ __forceinline__ void load_stage(
        __nv_bfloat16* st,
        const __nv_bfloat16* __restrict__ Ah, const __nv_bfloat16* __restrict__ Al,
        const __nv_bfloat16* __restrict__ Bh, const __nv_bfloat16* __restrict__ Bl,
        int m0, int n0, int kb, int tid) {
#pragma unroll
    for (int i = 0; i < 2; ++i) {
        int chunk = tid + i * 256;
        int row = chunk >> 2;
        int c8  = (chunk & 3) << 3;
        size_t ga = (size_t)(m0 + row) * K + kb + c8;
        size_t gb = (size_t)(n0 + row) * K + kb + c8;
        int so = row * SST + c8;
        cp16(st + so,             Ah + ga);
        cp16(st + PLANE + so,     Al + ga);
        cp16(st + 2 * PLANE + so, Bh + gb);
        cp16(st + 3 * PLANE + so, Bl + gb);
    }
}

// MODE: 0 = fp32 raw out; 1 = bias+relu -> bf16 hi/lo; 2 = bias+relu -> dot w5 -> atomicAdd
template<int K, int MODE>
__global__ __launch_bounds__(256, 2)
void hmma_gemm(const __nv_bfloat16* __restrict__ Ah,
               const __nv_bfloat16* __restrict__ Al,
               const __nv_bfloat16* __restrict__ Bh,
               const __nv_bfloat16* __restrict__ Bl,
               const float* __restrict__ bias,
               void* __restrict__ Cout,
               __nv_bfloat16* __restrict__ Clo,
               const float* __restrict__ w5) {
    extern __shared__ __nv_bfloat16 smem[];

    const int tid  = threadIdx.x;
    const int lane = tid & 31;
    const int wid  = tid >> 5;
    const int wm   = wid & 3;
    const int wn   = wid >> 2;
    const int m0   = blockIdx.y * 128;
    const int n0   = blockIdx.x * 128;
    const int lr   = lane >> 2;
    const int lq   = lane & 3;
    const int grp  = lane >> 3;
    const int rr   = lane & 7;

    const int a_row = wm * 32 + (grp & 1) * 8 + rr;
    const int a_kb  = (grp >> 1) * 8;
    const int b_row = wn * 64 + (grp >> 1) * 8 + rr;
    const int b_kb  = (grp & 1) * 8;

    float acc[2][8][4];
#pragma unroll
    for (int i = 0; i < 2; ++i)
#pragma unroll
        for (int j = 0; j < 8; ++j)
#pragma unroll
            for (int c = 0; c < 4; ++c) acc[i][j][c] = 0.f;

    constexpr int S = K / 32;
    load_stage<K>(smem, Ah, Al, Bh, Bl, m0, n0, 0, tid);
    cp_commit();

    for (int s = 0; s < S; ++s) {
        if (s + 1 < S) {
            load_stage<K>(smem + ((s + 1) & 1) * STAGE, Ah, Al, Bh, Bl,
                          m0, n0, (s + 1) * 32, tid);
            cp_commit();
            cp_wait<1>();
        } else {
            cp_wait<0>();
        }
        __syncthreads();

        const __nv_bfloat16* sAh = smem + (s & 1) * STAGE;
        const __nv_bfloat16* sAl = sAh + PLANE;
        const __nv_bfloat16* sBh = sAh + 2 * PLANE;
        const __nv_bfloat16* sBl = sAh + 3 * PLANE;

#pragma unroll
        for (int ks = 0; ks < 32; ks += 16) {
            u32 af[2][2][4];
#pragma unroll
            for (int ti = 0; ti < 2; ++ti) {
                ldsm4(af[ti][0], sAh + (a_row + ti * 16) * SST + ks + a_kb);
                ldsm4(af[ti][1], sAl + (a_row + ti * 16) * SST + ks + a_kb);
            }
#pragma unroll
            for (int jp = 0; jp < 4; ++jp) {
                u32 bh[4], bl[4];
                ldsm4(bh, sBh + (b_row + jp * 16) * SST + ks + b_kb);
                ldsm4(bl, sBl + (b_row + jp * 16) * SST + ks + b_kb);
#pragma unroll
                for (int ti = 0; ti < 2; ++ti) {
                    mma_bf16(acc[ti][2 * jp],     af[ti][0], bh);
                    mma_bf16(acc[ti][2 * jp],     af[ti][0], bl);
                    mma_bf16(acc[ti][2 * jp],     af[ti][1], bh);
                    mma_bf16(acc[ti][2 * jp + 1], af[ti][0], bh + 2);
                    mma_bf16(acc[ti][2 * jp + 1], af[ti][0], bl + 2);
                    mma_bf16(acc[ti][2 * jp + 1], af[ti][1], bh + 2);
                }
            }
        }
        __syncthreads();
    }

    // ---- epilogue ----
    if (MODE == 0) {
        float* C = (float*)Cout;
#pragma unroll
        for (int ti = 0; ti < 2; ++ti) {
            int row0 = m0 + wm * 32 + ti * 16 + lr;
#pragma unroll
            for (int tj = 0; tj < 8; ++tj) {
                int col0 = n0 + wn * 64 + tj * 8 + lq * 2;
#pragma unroll
                for (int half = 0; half < 2; ++half) {
                    size_t off = (size_t)(row0 + half * 8) * NHID + col0;
                    *reinterpret_cast<float2*>(C + off) =
                        make_float2(acc[ti][tj][half * 2 + 0],
                                    acc[ti][tj][half * 2 + 1]);
                }
            }
        }
    } else if (MODE == 1) {
        __nv_bfloat16* Chi = (__nv_bfloat16*)Cout;
#pragma unroll
        for (int ti = 0; ti < 2; ++ti) {
            int row0 = m0 + wm * 32 + ti * 16 + lr;
#pragma unroll
            for (int tj = 0; tj < 8; ++tj) {
                int col0 = n0 + wn * 64 + tj * 8 + lq * 2;
                float b0 = bias[col0], b1 = bias[col0 + 1];
#pragma unroll
                for (int half = 0; half < 2; ++half) {
                    size_t off = (size_t)(row0 + half * 8) * NHID + col0;
                    float v0 = fmaxf(acc[ti][tj][half * 2 + 0] + b0, 0.f);
                    float v1 = fmaxf(acc[ti][tj][half * 2 + 1] + b1, 0.f);
                    float h0 = __bfloat162float(__float2bfloat16(v0));
                    float h1 = __bfloat162float(__float2bfloat16(v1));
                    *reinterpret_cast<u32*>(Chi + off) = pack2(h0, h1);
                    *reinterpret_cast<u32*>(Clo + off) = pack2(v0 - h0, v1 - h1);
                }
            }
        }
    } else {
        float part[2][2][3];
#pragma unroll
        for (int ti = 0; ti < 2; ++ti)
#pragma unroll
            for (int h = 0; h < 2; ++h)
#pragma unroll
                for (int c = 0; c < 3; ++c) part[ti][h][c] = 0.f;

#pragma unroll
        for (int tj = 0; tj < 8; ++tj) {
            int col0 = n0 + wn * 64 + tj * 8 + lq * 2;
            float b0 = bias[col0], b1 = bias[col0 + 1];
            float w50[3], w51[3];
#pragma unroll
            for (int c = 0; c < 3; ++c) {
                w50[c] = w5[col0 * 3 + c];
                w51[c] = w5[(col0 + 1) * 3 + c];
            }
#pragma unroll
            for (int ti = 0; ti < 2; ++ti)
#pragma unroll
                for (int half = 0; half < 2; ++half) {
                    float v0 = fmaxf(acc[ti][tj][half * 2 + 0] + b0, 0.f);
                    float v1 = fmaxf(acc[ti][tj][half * 2 + 1] + b1, 0.f);
#pragma unroll
                    for (int c = 0; c < 3; ++c)
                        part[ti][half][c] += v0 * w50[c] + v1 * w51[c];
                }
        }
#pragma unroll
        for (int ti = 0; ti < 2; ++ti)
#pragma unroll
            for (int h = 0; h < 2; ++h)
#pragma unroll
                for (int c = 0; c < 3; ++c) {
                    float v = part[ti][h][c];
                    v += __shfl_xor_sync(0xffffffffu, v, 1);
                    v += __shfl_xor_sync(0xffffffffu, v, 2);
                    part[ti][h][c] = v;
                }
        float* sp = reinterpret_cast<float*>(smem);
        if (lq == 0) {
#pragma unroll
            for (int ti = 0; ti < 2; ++ti)
#pragma unroll
                for (int h = 0; h < 2; ++h) {
                    int row = wm * 32 + ti * 16 + h * 8 + lr;
#pragma unroll
                    for (int c = 0; c < 3; ++c)
                        sp[(wn * 128 + row) * 3 + c] = part[ti][h][c];
                }
        }
        __syncthreads();
        for (int i = tid; i < 384; i += 256) {
            float v = sp[i] + sp[384 + i];
            atomicAdd(&g_PRED[(size_t)(m0 + i / 3) * 3 + (i % 3)], v);
        }
    }
}

// ---------------- output combine --------------------------------------------
__global__ __launch_bounds__(256)
void out_combine(const float* __restrict__ b5, float* __restrict__ out) {
    int q = blockIdx.x * 256 + threadIdx.x;
    float ar[4], tot = 0.f;
#pragma unroll
    for (int s = 0; s < 4; ++s) { ar[s] = g_AREA[(size_t)s * Q + q]; tot += ar[s]; }
    float r0 = 0.f, r1 = 0.f, r2 = 0.f;
#pragma unroll
    for (int s = 0; s < 4; ++s) {
        float wgt = ar[3 - s] / tot;
        size_t base = ((size_t)s * Q + q) * 3;
        r0 += (g_PRED[base + 0] + b5[0]) * wgt;
        r1 += (g_PRED[base + 1] + b5[1]) * wgt;
        r2 += (g_PRED[base + 2] + b5[2]) * wgt;
    }
    out[(size_t)q * 3 + 0] = r0;
    out[(size_t)q * 3 + 1] = r1;
    out[(size_t)q * 3 + 2] = r2;
}

// ---------------- launch ----------------------------------------------------
extern "C" void kernel_launch(void* const* d_in, const int* in_sizes, int n_in,
                              void* d_out, int out_size) {
    const float* F    = (const float*)d_in[0];
    const float* loc  = (const float*)d_in[1];
    const float* cell = (const float*)d_in[2];
    const float* w1 = (const float*)d_in[3];
    const float* b1 = (const float*)d_in[4];
    const float* w2 = (const float*)d_in[5];
    const float* b2 = (const float*)d_in[6];
    const float* w3 = (const float*)d_in[7];
    const float* b3 = (const float*)d_in[8];
    const float* w4 = (const float*)d_in[9];
    const float* b4 = (const float*)d_in[10];
    const float* w5 = (const float*)d_in[11];
    const float* b5 = (const float*)d_in[12];
    float* out = (float*)d_out;

    __nv_bfloat16 *XCh, *XCl, *HAh, *HAl, *HBh, *HBl;
    __nv_bfloat16 *W1h, *W1l, *W2h, *W2l, *W3h, *W3l, *W4h, *W4l;
    float *G, *PRED;
    cudaGetSymbolAddress((void**)&XCh, g_XCh); cudaGetSymbolAddress((void**)&XCl, g_XCl);
    cudaGetSymbolAddress((void**)&G,   g_G);
    cudaGetSymbolAddress((void**)&PRED, g_PRED);
    cudaGetSymbolAddress((void**)&HAh, g_HAh); cudaGetSymbolAddress((void**)&HAl, g_HAl);
    cudaGetSymbolAddress((void**)&HBh, g_HBh); cudaGetSymbolAddress((void**)&HBl, g_HBl);
    cudaGetSymbolAddress((void**)&W1h, g_W1h); cudaGetSymbolAddress((void**)&W1l, g_W1l);
    cudaGetSymbolAddress((void**)&W2h, g_W2h); cudaGetSymbolAddress((void**)&W2l, g_W2l);
    cudaGetSymbolAddress((void**)&W3h, g_W3h); cudaGetSymbolAddress((void**)&W3l, g_W3l);
    cudaGetSymbolAddress((void**)&W4h, g_W4h); cudaGetSymbolAddress((void**)&W4l, g_W4l);

    cudaFuncSetAttribute(hmma_gemm<KC, 0>,
        cudaFuncAttributeMaxDynamicSharedMemorySize, SMEMB);
    cudaFuncSetAttribute(hmma_gemm<256, 1>,
        cudaFuncAttributeMaxDynamicSharedMemorySize, SMEMB);
    cudaFuncSetAttribute(hmma_gemm<256, 2>,
        cudaFuncAttributeMaxDynamicSharedMemorySize, SMEMB);

    cudaMemsetAsync(PRED, 0, (size_t)MROWS * 3 * sizeof(float));

    const int PREP_ELEMS = 256 * KC + 3 * 256 * 256;
    prep_all_kernel<<<(PREP_ELEMS + 255) / 256, 256>>>(w1, w2, w3, w4);

    im2col_kernel<<<NPIX, KC>>>(F);
    rowinfo_kernel<<<MROWS / 256, 256>>>(loc, cell);

    // conv GEMM: G[65536,256] = XC @ W1[0:288]^T
    hmma_gemm<KC, 0><<<dim3(2, NPIX / 128), 256, SMEMB>>>(
        XCh, XCl, W1h, W1l, nullptr, G, nullptr, nullptr);

    // combine: H1 = relu(G[p] + rank-4 update + b1)
    combine2_kernel<<<MROWS / 4, 256>>>(w1, b1, HAh, HAl);

    dim3 ggrid(2, MROWS / 128);
    hmma_gemm<256, 1><<<ggrid, 256, SMEMB>>>(HAh, HAl, W2h, W2l, b2, HBh, HBl, nullptr);
    hmma_gemm<256, 1><<<ggrid, 256, SMEMB>>>(HBh, HBl, W3h, W3l, b3, HAh, HAl, nullptr);
    hmma_gemm<256, 2><<<ggrid, 256, SMEMB>>>(HAh, HAl, W4h, W4l, b4, nullptr, nullptr, w5);

    out_combine<<<Q / 256, 256>>>(b5, out);
}